// round 5
// baseline (speedup 1.0000x reference)
#include <cuda_runtime.h>
#include <stdint.h>

// UniformShardedEmbeddingBags: weights [E,T,D] fp32, indices [B,T,L] int32 -> out [B,T,D] fp32
// E=200000, T=16, D=64, B=4096, L=20
#define EB_E 200000
#define EB_T 16
#define EB_D 64
#define EB_L 20
#define EB_B 4096

// One warp processes TWO bags of the same table concurrently. Each lane owns one
// float2 (8B) slot; a row gather is 32 lanes x 8B = two coalesced 128B lines.
// The 2x20 row loads are all independent -> with the register cap removed
// (no minBlocks clamp) ptxas can software-pipeline ~16+ loads in flight per
// warp. Purpose: deepen DRAM controller queues to kill the 26% DRAM-idle
// (channel-imbalance starvation) seen at 32 regs.
//
// Grid stays TABLE-MAJOR (256 blocks per table, 16 bags per block) so the
// concurrent working set spans ~2-3 tables and L2 keeps capturing the ~1.22x
// per-table row reuse.
__global__ __launch_bounds__(256) void embbag_kernel(
    const float* __restrict__ weights,
    const int* __restrict__ indices,
    float* __restrict__ out)
{
    const int warp = threadIdx.x >> 5;                  // 0..7
    const int lane = threadIdx.x & 31;

    const int t  = blockIdx.x >> 8;                     // table 0..15 (256 blocks each)
    const int b0 = ((blockIdx.x & 255) << 4) + (warp << 1);  // batch, 2 per warp
    const int b1 = b0 + 1;

    const int bag0 = b0 * EB_T + t;
    const int bag1 = b1 * EB_T + t;

    // Lanes 0..19 fetch each bag's indices (one coalesced transaction per bag).
    int idx0 = 0, idx1 = 0;
    if (lane < EB_L) {
        idx0 = __ldg(indices + (size_t)bag0 * EB_L + lane);
        idx1 = __ldg(indices + (size_t)bag1 * EB_L + lane);
    }

    const float2* wbase = reinterpret_cast<const float2*>(weights) + lane;

    float2 acc0 = make_float2(0.f, 0.f);
    float2 acc1 = make_float2(0.f, 0.f);

#pragma unroll
    for (int l = 0; l < EB_L; ++l) {
        int e0 = __shfl_sync(0xFFFFFFFFu, idx0, l);
        int e1 = __shfl_sync(0xFFFFFFFFu, idx1, l);
        float2 v0 = __ldg(wbase + ((size_t)e0 * EB_T + t) * (EB_D / 2));
        float2 v1 = __ldg(wbase + ((size_t)e1 * EB_T + t) * (EB_D / 2));
        acc0.x += v0.x; acc0.y += v0.y;
        acc1.x += v1.x; acc1.y += v1.y;
    }

    reinterpret_cast<float2*>(out)[(size_t)bag0 * 32 + lane] = acc0;
    reinterpret_cast<float2*>(out)[(size_t)bag1 * 32 + lane] = acc1;
}

extern "C" void kernel_launch(void* const* d_in, const int* in_sizes, int n_in,
                              void* d_out, int out_size)
{
    // weights = 204,800,000 elems ; indices = 1,310,720 elems
    const float* weights = (const float*)d_in[0];
    const int*   indices = (const int*)d_in[1];
    if (n_in >= 2 && in_sizes[0] < in_sizes[1]) {
        weights = (const float*)d_in[1];
        indices = (const int*)d_in[0];
    }
    float* out = (float*)d_out;

    const int block = 256;                 // 8 warps x 2 bags = 16 bags per block
    const int grid = EB_T * 256;           // 4096 blocks, table-major
    embbag_kernel<<<grid, block>>>(weights, indices, out);
}

// round 7
// speedup vs baseline: 1.0700x; 1.0700x over previous
#include <cuda_runtime.h>
#include <stdint.h>

// UniformShardedEmbeddingBags: weights [E,T,D] fp32, indices [B,T,L] int32 -> out [B,T,D] fp32
// E=200000, T=16, D=64, B=4096, L=20
#define EB_E 200000
#define EB_T 16
#define EB_D 64
#define EB_L 20
#define EB_B 4096

// One warp per bag, each lane owns one float2 (8B) slot of the 256B row
// (32 lanes x 8B = two coalesced 128B lines per gathered row).
//
// PHASE-SPLIT to force MLP: all 20 row loads are issued into an explicit
// register array v[20] BEFORE any accumulation. This removes the accumulator
// dependency from the load stream, so ptxas must keep all 20 LDG.64 in flight
// (~40 data regs live). Occupancy drops to ~50%, but in-flight row gathers per
// SM rise ~2.5x (->~640) to fight the 26-28% DRAM-idle (request starvation /
// channel queue imbalance) seen in R3-R5.
//
// Grid stays TABLE-MAJOR so L2 keeps capturing the ~1.22x per-table row reuse.
__global__ __launch_bounds__(256) void embbag_kernel(
    const float* __restrict__ weights,
    const int* __restrict__ indices,
    float* __restrict__ out)
{
    const int warp = threadIdx.x >> 5;                  // 0..7
    const int lane = threadIdx.x & 31;

    const int t = blockIdx.x >> 9;                      // table 0..15 (512 blocks each)
    const int b = ((blockIdx.x & 511) << 3) + warp;     // batch 0..4095
    const int bag = b * EB_T + t;

    // Lanes 0..19 fetch this bag's indices; one coalesced transaction.
    int myidx = 0;
    if (lane < EB_L) myidx = __ldg(indices + (size_t)bag * EB_L + lane);

    const float2* wbase = reinterpret_cast<const float2*>(weights) + lane;

    // Phase 1: issue ALL row loads (no consumer in between).
    float2 v[EB_L];
#pragma unroll
    for (int l = 0; l < EB_L; ++l) {
        int e = __shfl_sync(0xFFFFFFFFu, myidx, l);
        v[l] = __ldg(wbase + ((size_t)e * EB_T + t) * (EB_D / 2));
    }

    // Phase 2: reduce.
    float accx = 0.f, accy = 0.f;
#pragma unroll
    for (int l = 0; l < EB_L; ++l) {
        accx += v[l].x;
        accy += v[l].y;
    }

    reinterpret_cast<float2*>(out)[(size_t)bag * 32 + lane] = make_float2(accx, accy);
}

extern "C" void kernel_launch(void* const* d_in, const int* in_sizes, int n_in,
                              void* d_out, int out_size)
{
    // weights = 204,800,000 elems ; indices = 1,310,720 elems
    const float* weights = (const float*)d_in[0];
    const int*   indices = (const int*)d_in[1];
    if (n_in >= 2 && in_sizes[0] < in_sizes[1]) {
        weights = (const float*)d_in[1];
        indices = (const int*)d_in[0];
    }
    float* out = (float*)d_out;

    const int block = 256;                 // 8 warps = 8 bags per block
    const int grid = EB_T * 512;           // 8192 blocks, table-major
    embbag_kernel<<<grid, block>>>(weights, indices, out);
}